// round 14
// baseline (speedup 1.0000x reference)
#include <cuda_runtime.h>
#include <cuda_bf16.h>
#include <cuda_fp8.h>
#include <cstdint>

#define N_PTS 9216
#define DD 256
#define KROW 64            // 60 e4m3 data dims + 4 norm slots (64B row)
#define GRID_T 72
#define NT 2628            // 72*73/2 triangular tiles
#define ASTR 80            // smem row stride bytes (64B data + 16B pad, conflict-free LDSM)
#define THR (-13.0f)       // acc >= THR <=> d2hat <= 26 (covers all d_full <= 4)
#define POSV ((float)(1.0 / 360.0))
#define NEGV ((float)(-0.5 / 8855.0))

__device__ uint8_t g_XA[N_PTS * KROW];   // [x60, -q1, -q2, 1, 1]
__device__ uint8_t g_XB[N_PTS * KROW];   // [x60, 1, 1, -q1, -q2]
__device__ float g_partials[NT];

// ------- prep: 4 threads/row; quantize dims 0..59; embed 2-term norm -------
__global__ void __launch_bounds__(256) prep_kernel(const float* __restrict__ images) {
    int tid = threadIdx.x;
    int row = (blockIdx.x * 256 + tid) >> 2;   // 4 threads per row
    int p = tid & 3;                           // bytes/dims [16p, 16p+16)
    const float4* src = (const float4*)(images + (size_t)row * DD + p * 16);
    float4 v[4];
    #pragma unroll
    for (int k = 0; k < 4; k++) v[k] = src[k];

    uint8_t qb[16];
    float s8 = 0.0f;
    int nd = (p == 3) ? 12 : 16;               // p==3: dims 48..59 only
    #pragma unroll
    for (int k = 0; k < 4; k++) {
        float va[4] = {v[k].x, v[k].y, v[k].z, v[k].w};
        #pragma unroll
        for (int c = 0; c < 4; c++) {
            int d = k * 4 + c;
            if (d < nd) {
                uint8_t e = __nv_cvt_float_to_fp8(va[c], __NV_SATFINITE, __NV_E4M3);
                qb[d] = e;
                float dq = __half2float(__nv_cvt_fp8_to_halfraw(e, __NV_E4M3));
                s8 = fmaf(dq, dq, s8);
            } else {
                qb[d] = 0;
            }
        }
    }
    // reduce subset norm across the 4-lane row group
    s8 += __shfl_xor_sync(0xffffffffu, s8, 1);
    s8 += __shfl_xor_sync(0xffffffffu, s8, 2);

    // two-term e4m3 expansion of sq/2: q1 + q2 ~= sq/2 with error <= 0.0625
    float h = 0.5f * s8;
    uint8_t u1 = __nv_cvt_float_to_fp8(h, __NV_SATFINITE, __NV_E4M3);
    float q1v = __half2float(__nv_cvt_fp8_to_halfraw(u1, __NV_E4M3));
    uint8_t u2 = __nv_cvt_float_to_fp8(h - q1v, __NV_SATFINITE, __NV_E4M3);
    const uint8_t ONE = 0x38;                  // e4m3 1.0
    uint8_t n1 = u1 ^ 0x80, n2 = u2 ^ 0x80;    // negate

    // A variant: slots [60]=-q1, [61]=-q2, [62]=1, [63]=1
    if (p == 3) { qb[12] = n1; qb[13] = n2; qb[14] = ONE; qb[15] = ONE; }
    *(uint4*)(g_XA + (size_t)row * KROW + p * 16) = *(uint4*)qb;
    // B variant: slots [60]=1, [61]=1, [62]=-q1, [63]=-q2
    if (p == 3) { qb[12] = ONE; qb[13] = ONE; qb[14] = n1; qb[15] = n2; }
    *(uint4*)(g_XB + (size_t)row * KROW + p * 16) = *(uint4*)qb;
}

// correction = sim(d2) + 1.0027, exact fp32, for d2 <= 16
__device__ __forceinline__ float corr_fn(float d2) {
    d2 = fmaxf(d2, 0.0f);
    float dist = (d2 > 0.0f) ? sqrtf(d2) : 0.0f;
    float t = 5.0f * (1.0f - dist);
    float sp = (t > 0.0f) ? (t + log1pf(expf(-t))) : log1pf(expf(t));
    return 0.4f * sp;
}
__device__ __forceinline__ float maskval(int i, int j) {
    int ci0 = i / 96, ci1 = i - ci0 * 96;
    int cj0 = j / 96, cj1 = j - cj0 * 96;
    int d0 = abs(ci0 - cj0); d0 = min(d0, 96 - d0);
    int d1 = abs(ci1 - cj1); d1 = min(d1, 96 - d1);
    return (d0 <= 9 && d1 <= 9) ? POSV : NEGV;
}

// ------ screening GEMM (K=64 fp8, norms embedded) + max-tree + rescue ------
__global__ void __launch_bounds__(256, 2)
pair_kernel(const float* __restrict__ images) {
    __shared__ uint8_t As[128 * ASTR];
    __shared__ uint8_t Bs[128 * ASTR];
    __shared__ float wsum[8];

    // triangular tile decode
    int t = blockIdx.x;
    int by = 0, rem = t;
    while (rem >= GRID_T - by) { rem -= GRID_T - by; by++; }
    int bx = by + rem;
    int i0 = by * 128, j0 = bx * 128;

    int tid  = threadIdx.x;
    int wid  = tid >> 5;
    int lane = tid & 31;
    int g  = lane >> 2;
    int tg = lane & 3;
    int wm = (wid >> 1) * 32;
    int wn = (wid & 1) * 64;

    // tile load: 128 rows x 64B each side; thread -> (row, 32B half)
    {
        int r = tid >> 1, h = (tid & 1) * 32;
        const uint8_t* sa = g_XA + (size_t)(i0 + r) * KROW + h;
        const uint8_t* sb = g_XB + (size_t)(j0 + r) * KROW + h;
        uint4 a0 = *(const uint4*)sa;
        uint4 a1 = *(const uint4*)(sa + 16);
        uint4 b0 = *(const uint4*)sb;
        uint4 b1 = *(const uint4*)(sb + 16);
        *(uint4*)(As + r * ASTR + h)      = a0;
        *(uint4*)(As + r * ASTR + h + 16) = a1;
        *(uint4*)(Bs + r * ASTR + h)      = b0;
        *(uint4*)(Bs + r * ASTR + h + 16) = b1;
    }
    __syncthreads();

    // ldmatrix addressing (proven geometry)
    int quad = lane >> 3, rw = lane & 7;
    uint32_t As_u, Bs_u;
    asm("{ .reg .u64 t; cvta.to.shared.u64 t, %1; cvt.u32.u64 %0, t; }" : "=r"(As_u) : "l"(As));
    asm("{ .reg .u64 t; cvta.to.shared.u64 t, %1; cvt.u32.u64 %0, t; }" : "=r"(Bs_u) : "l"(Bs));
    uint32_t aAddr = As_u + (uint32_t)((wm + rw + (quad & 1) * 8) * ASTR + (quad >> 1) * 16);
    uint32_t bAddr = Bs_u + (uint32_t)((wn + rw + ((quad >> 1) & 1) * 8) * ASTR + (quad & 1) * 16);

    float acc[2][8][4];
    #pragma unroll
    for (int a = 0; a < 2; a++)
        #pragma unroll
        for (int b = 0; b < 8; b++)
            #pragma unroll
            for (int c = 0; c < 4; c++) acc[a][b][c] = 0.0f;

    #pragma unroll
    for (int ksb = 0; ksb < KROW; ksb += 32) {       // 2 k32 steps
        uint32_t afr[2][4];
        #pragma unroll
        for (int mf = 0; mf < 2; mf++) {
            uint32_t ad = aAddr + (uint32_t)(mf * 16 * ASTR + ksb);
            asm volatile("ldmatrix.sync.aligned.m8n8.x4.shared.b16 {%0,%1,%2,%3}, [%4];"
                         : "=r"(afr[mf][0]), "=r"(afr[mf][1]),
                           "=r"(afr[mf][2]), "=r"(afr[mf][3]) : "r"(ad));
        }
        uint32_t bfr[8][2];
        #pragma unroll
        for (int p = 0; p < 4; p++) {
            uint32_t bd = bAddr + (uint32_t)(p * 16 * ASTR + ksb);
            asm volatile("ldmatrix.sync.aligned.m8n8.x4.shared.b16 {%0,%1,%2,%3}, [%4];"
                         : "=r"(bfr[2 * p][0]), "=r"(bfr[2 * p][1]),
                           "=r"(bfr[2 * p + 1][0]), "=r"(bfr[2 * p + 1][1]) : "r"(bd));
        }
        #pragma unroll
        for (int mf = 0; mf < 2; mf++)
            #pragma unroll
            for (int nf = 0; nf < 8; nf++) {
                asm volatile(
                    "mma.sync.aligned.m16n8k32.row.col.f32.e4m3.e4m3.f32 "
                    "{%0,%1,%2,%3}, {%4,%5,%6,%7}, {%8,%9}, {%0,%1,%2,%3};\n"
                    : "+f"(acc[mf][nf][0]), "+f"(acc[mf][nf][1]),
                      "+f"(acc[mf][nf][2]), "+f"(acc[mf][nf][3])
                    : "r"(afr[mf][0]), "r"(afr[mf][1]),
                      "r"(afr[mf][2]), "r"(afr[mf][3]),
                      "r"(bfr[nf][0]), "r"(bfr[nf][1]));
            }
    }

    // ---- epilogue: acc = dot60 - sqi/2 - sqj/2 ~= -d2hat/2; max-tree screen
    float local = 0.0f;
    float m16[16];
    #pragma unroll
    for (int mf = 0; mf < 2; mf++)
        #pragma unroll
        for (int nf = 0; nf < 8; nf++)
            m16[mf * 8 + nf] = fmaxf(fmaxf(acc[mf][nf][0], acc[mf][nf][1]),
                                     fmaxf(acc[mf][nf][2], acc[mf][nf][3]));
    #pragma unroll
    for (int s = 8; s > 0; s >>= 1)
        #pragma unroll
        for (int k = 0; k < 8; k++)
            if (k < s) m16[k] = fmaxf(m16[k], m16[k + s]);

    if (__any_sync(0xffffffffu, m16[0] >= THR)) {    // diag fragments + ~0.02 pairs
        #pragma unroll 1
        for (int mf = 0; mf < 2; mf++) {
            #pragma unroll 1
            for (int nf = 0; nf < 8; nf++) {
                #pragma unroll
                for (int q = 0; q < 4; q++) {
                    if (acc[mf][nf][q] >= THR) {
                        int i = i0 + wm + mf * 16 + g + (q >> 1) * 8;
                        int j = j0 + wn + nf * 8 + 2 * tg + (q & 1);
                        if (i < j) {                 // count once, weight x2
                            const float4* xa = (const float4*)(images + (size_t)i * DD);
                            const float4* xb = (const float4*)(images + (size_t)j * DD);
                            float sqi = 0.0f, sqj = 0.0f, dot = 0.0f;
                            #pragma unroll 8
                            for (int u = 0; u < 64; u++) {
                                float4 a = xa[u], b = xb[u];
                                sqi = fmaf(a.x, a.x, sqi); sqi = fmaf(a.y, a.y, sqi);
                                sqi = fmaf(a.z, a.z, sqi); sqi = fmaf(a.w, a.w, sqi);
                                sqj = fmaf(b.x, b.x, sqj); sqj = fmaf(b.y, b.y, sqj);
                                sqj = fmaf(b.z, b.z, sqj); sqj = fmaf(b.w, b.w, sqj);
                                dot = fmaf(a.x, b.x, dot); dot = fmaf(a.y, b.y, dot);
                                dot = fmaf(a.z, b.z, dot); dot = fmaf(a.w, b.w, dot);
                            }
                            float d2 = fmaxf(sqi + sqj - 2.0f * dot, 0.0f);
                            if (d2 <= 16.0f)
                                local = fmaf(2.0f * corr_fn(d2), maskval(i, j), local);
                        }
                    }
                }
            }
        }
    }

    #pragma unroll
    for (int o = 16; o > 0; o >>= 1) local += __shfl_xor_sync(0xffffffffu, local, o);
    if (lane == 0) wsum[wid] = local;
    __syncthreads();
    if (tid == 0) {
        float s = 0.0f;
        #pragma unroll
        for (int w = 0; w < 8; w++) s += wsum[w];
        g_partials[blockIdx.x] = s;
    }
}

// ---------------- final reduce + closed-form base term ---------------------
__global__ void reduce_kernel(float* __restrict__ out) {
    int t = threadIdx.x;  // 256
    float s = 0.0f;
    for (int i = t; i < NT; i += 256) s += g_partials[i];
    #pragma unroll
    for (int o = 16; o > 0; o >>= 1) s += __shfl_xor_sync(0xffffffffu, s, o);
    __shared__ float ws[8];
    if ((t & 31) == 0) ws[t >> 5] = s;
    __syncthreads();
    if (t == 0) {
        float tot = 0.0f;
        #pragma unroll
        for (int w = 0; w < 8; w++) tot += ws[w];
        // off-diag sim == -1.0027f exactly; sum(mask) = N*(360*POSV + 8855*NEGV)
        double masksum = 9216.0 * (360.0 * (double)POSV + 8855.0 * (double)NEGV);
        double base = (double)(-1.0027f) * masksum;
        out[0] = (float)(((double)tot + base) / 9216.0);
    }
}

extern "C" void kernel_launch(void* const* d_in, const int* in_sizes, int n_in,
                              void* d_out, int out_size) {
    const float* images = (const float*)d_in[0];   // [9216,1,16,16] fp32
    (void)in_sizes; (void)n_in;
    prep_kernel<<<N_PTS * 4 / 256, 256>>>(images);
    pair_kernel<<<NT, 256>>>(images);
    reduce_kernel<<<1, 256>>>((float*)d_out);
}

// round 15
// speedup vs baseline: 1.3935x; 1.3935x over previous
#include <cuda_runtime.h>
#include <cuda_bf16.h>
#include <cuda_fp8.h>
#include <cstdint>

#define N_PTS 9216
#define DD 256
#define KSUB 64            // screening subset: dims 0..63 (d2_full >= d2_sub, strict)
#define GRID_T 72
#define NT 2628            // 72*73/2 triangular tiles
#define ASTR 80            // smem row stride bytes (64B data + 16B pad, conflict-free LDSM)
#define POSV ((float)(1.0 / 360.0))
#define NEGV ((float)(-0.5 / 8855.0))

__device__ uint8_t g_X8[N_PTS * KSUB];     // e4m3 of first 64 dims
__device__ float g_sq8[N_PTS];             // subset norms of DEQUANTIZED values (exact screen)
__device__ float g_partials[NT];

// ------- prep: 8 threads/row, dims 0..63 ONLY (2.4 MB read) ----------------
__global__ void __launch_bounds__(256) prep_kernel(const float* __restrict__ images) {
    int tid = threadIdx.x;
    int row = (blockIdx.x * 256 + tid) >> 3;   // 8 threads per row
    int p = tid & 7;                           // dims [8p, 8p+8)
    const float4* src = (const float4*)(images + (size_t)row * DD + p * 8);
    float4 v0 = src[0], v1 = src[1];
    float vals[8] = {v0.x, v0.y, v0.z, v0.w, v1.x, v1.y, v1.z, v1.w};

    uint32_t q[2] = {0, 0};
    float s8 = 0.0f;
    #pragma unroll
    for (int k = 0; k < 8; k++) {
        uint8_t e = __nv_cvt_float_to_fp8(vals[k], __NV_SATFINITE, __NV_E4M3);
        q[k >> 2] |= (uint32_t)e << ((k & 3) * 8);
        float dq = __half2float(__nv_cvt_fp8_to_halfraw(e, __NV_E4M3));
        s8 = fmaf(dq, dq, s8);
    }
    *(uint2*)(g_X8 + (size_t)row * KSUB + p * 8) = make_uint2(q[0], q[1]);

    s8 += __shfl_xor_sync(0xffffffffu, s8, 1);
    s8 += __shfl_xor_sync(0xffffffffu, s8, 2);
    s8 += __shfl_xor_sync(0xffffffffu, s8, 4);
    if (p == 0) g_sq8[row] = s8;
}

// correction = sim(d2) + 1.0027, exact fp32, for d2 <= 16
__device__ __forceinline__ float corr_fn(float d2) {
    d2 = fmaxf(d2, 0.0f);
    float dist = (d2 > 0.0f) ? sqrtf(d2) : 0.0f;
    float t = 5.0f * (1.0f - dist);
    float sp = (t > 0.0f) ? (t + log1pf(expf(-t))) : log1pf(expf(t));
    return 0.4f * sp;
}
__device__ __forceinline__ float maskval(int i, int j) {
    int ci0 = i / 96, ci1 = i - ci0 * 96;
    int cj0 = j / 96, cj1 = j - cj0 * 96;
    int d0 = abs(ci0 - cj0); d0 = min(d0, 96 - d0);
    int d1 = abs(ci1 - cj1); d1 = min(d1, 96 - d1);
    return (d0 <= 9 && d1 <= 9) ? POSV : NEGV;
}

// closed-form triangular decode: start(by) = by*(145-by)/2
__device__ __forceinline__ void decode_tile(int t, int& by, int& bx) {
    int b = (int)floorf(0.5f * (145.0f - sqrtf(fmaxf(21025.0f - 8.0f * (float)t, 0.0f))));
    b = max(0, min(b, GRID_T - 1));
    while (b > 0 && t < (b * (145 - b)) / 2) b--;
    while (t >= ((b + 1) * (144 - b)) / 2) b++;
    by = b;
    bx = b + (t - (b * (145 - b)) / 2);
}

// ---------------- screening GEMM (K=64 fp8) + exact rescue (R13 proven) ----
__global__ void __launch_bounds__(256, 2)
pair_kernel(const float* __restrict__ images) {
    __shared__ uint8_t As[128 * ASTR];
    __shared__ uint8_t Bs[128 * ASTR];
    __shared__ float sSq8I[128];
    __shared__ float sSq8J[128];
    __shared__ float wsum[8];

    int by, bx;
    decode_tile(blockIdx.x, by, bx);
    int i0 = by * 128, j0 = bx * 128;

    int tid  = threadIdx.x;
    int wid  = tid >> 5;
    int lane = tid & 31;
    int g  = lane >> 2;
    int tg = lane & 3;
    int wm = (wid >> 1) * 32;
    int wn = (wid & 1) * 64;

    // tile loads FIRST (deep MLP at CTA start): 2 x (row, 32B half) per thread
    int ldr_r = tid >> 1, ldr_h = (tid & 1) * 32;
    const uint8_t* sa = g_X8 + (size_t)(i0 + ldr_r) * KSUB + ldr_h;
    const uint8_t* sb = g_X8 + (size_t)(j0 + ldr_r) * KSUB + ldr_h;
    uint4 a0 = *(const uint4*)sa;
    uint4 a1 = *(const uint4*)(sa + 16);
    uint4 b0 = *(const uint4*)sb;
    uint4 b1 = *(const uint4*)(sb + 16);

    // norm loads issue after (independent; overlap the tile LDGs)
    if (tid < 128) sSq8I[tid] = g_sq8[i0 + tid];
    else           sSq8J[tid - 128] = g_sq8[j0 + (tid - 128)];

    *(uint4*)(As + ldr_r * ASTR + ldr_h)      = a0;
    *(uint4*)(As + ldr_r * ASTR + ldr_h + 16) = a1;
    *(uint4*)(Bs + ldr_r * ASTR + ldr_h)      = b0;
    *(uint4*)(Bs + ldr_r * ASTR + ldr_h + 16) = b1;
    __syncthreads();

    // ldmatrix addressing (proven geometry)
    int quad = lane >> 3, rw = lane & 7;
    uint32_t As_u, Bs_u;
    asm("{ .reg .u64 t; cvta.to.shared.u64 t, %1; cvt.u32.u64 %0, t; }" : "=r"(As_u) : "l"(As));
    asm("{ .reg .u64 t; cvta.to.shared.u64 t, %1; cvt.u32.u64 %0, t; }" : "=r"(Bs_u) : "l"(Bs));
    uint32_t aAddr = As_u + (uint32_t)((wm + rw + (quad & 1) * 8) * ASTR + (quad >> 1) * 16);
    uint32_t bAddr = Bs_u + (uint32_t)((wn + rw + ((quad >> 1) & 1) * 8) * ASTR + (quad & 1) * 16);

    float acc[2][8][4];
    #pragma unroll
    for (int a = 0; a < 2; a++)
        #pragma unroll
        for (int b = 0; b < 8; b++)
            #pragma unroll
            for (int c = 0; c < 4; c++) acc[a][b][c] = 0.0f;

    #pragma unroll
    for (int ksb = 0; ksb < KSUB; ksb += 32) {       // 2 k32 steps
        uint32_t afr[2][4];
        #pragma unroll
        for (int mf = 0; mf < 2; mf++) {
            uint32_t ad = aAddr + (uint32_t)(mf * 16 * ASTR + ksb);
            asm volatile("ldmatrix.sync.aligned.m8n8.x4.shared.b16 {%0,%1,%2,%3}, [%4];"
                         : "=r"(afr[mf][0]), "=r"(afr[mf][1]),
                           "=r"(afr[mf][2]), "=r"(afr[mf][3]) : "r"(ad));
        }
        uint32_t bfr[8][2];
        #pragma unroll
        for (int p = 0; p < 4; p++) {
            uint32_t bd = bAddr + (uint32_t)(p * 16 * ASTR + ksb);
            asm volatile("ldmatrix.sync.aligned.m8n8.x4.shared.b16 {%0,%1,%2,%3}, [%4];"
                         : "=r"(bfr[2 * p][0]), "=r"(bfr[2 * p][1]),
                           "=r"(bfr[2 * p + 1][0]), "=r"(bfr[2 * p + 1][1]) : "r"(bd));
        }
        #pragma unroll
        for (int mf = 0; mf < 2; mf++)
            #pragma unroll
            for (int nf = 0; nf < 8; nf++) {
                asm volatile(
                    "mma.sync.aligned.m16n8k32.row.col.f32.e4m3.e4m3.f32 "
                    "{%0,%1,%2,%3}, {%4,%5,%6,%7}, {%8,%9}, {%0,%1,%2,%3};\n"
                    : "+f"(acc[mf][nf][0]), "+f"(acc[mf][nf][1]),
                      "+f"(acc[mf][nf][2]), "+f"(acc[mf][nf][3])
                    : "r"(afr[mf][0]), "r"(afr[mf][1]),
                      "r"(afr[mf][2]), "r"(afr[mf][3]),
                      "r"(bfr[nf][0]), "r"(bfr[nf][1]));
            }
    }

    // ---- epilogue: exact quantized-space screen, d2hat <= 32 => rescue ----
    // d2_full >= d2_sub(true); quant slack: d<=4 => d2hat <= 29.2 < 32.
    float local = 0.0f;
    #pragma unroll
    for (int mf = 0; mf < 2; mf++) {
        int r0 = wm + mf * 16 + g;
        float sqa = sSq8I[r0];
        float sqb = sSq8I[r0 + 8];
        #pragma unroll
        for (int nf = 0; nf < 8; nf++) {
            int cl = wn + nf * 8 + 2 * tg;
            float sj0 = sSq8J[cl];
            float sj1 = sSq8J[cl + 1];
            float d00 = fmaf(-2.0f, acc[mf][nf][0], sqa + sj0);
            float d01 = fmaf(-2.0f, acc[mf][nf][1], sqa + sj1);
            float d10 = fmaf(-2.0f, acc[mf][nf][2], sqb + sj0);
            float d11 = fmaf(-2.0f, acc[mf][nf][3], sqb + sj1);
            float mn = fminf(fminf(d00, d01), fminf(d10, d11));
            if (mn <= 32.0f) {          // ~only diagonal fragments trigger
                #pragma unroll
                for (int q = 0; q < 4; q++) {
                    float d2f = (q == 0) ? d00 : (q == 1) ? d01 : (q == 2) ? d10 : d11;
                    if (d2f <= 32.0f) {
                        int i = i0 + r0 + (q >> 1) * 8;
                        int j = j0 + cl + (q & 1);
                        if (i < j) {    // count once, weight x2 (symmetry)
                            const float4* xa = (const float4*)(images + (size_t)i * DD);
                            const float4* xb = (const float4*)(images + (size_t)j * DD);
                            float sqi = 0.0f, sqj = 0.0f, dot = 0.0f;
                            #pragma unroll 8
                            for (int u = 0; u < 64; u++) {
                                float4 a = xa[u], b = xb[u];
                                sqi = fmaf(a.x, a.x, sqi); sqi = fmaf(a.y, a.y, sqi);
                                sqi = fmaf(a.z, a.z, sqi); sqi = fmaf(a.w, a.w, sqi);
                                sqj = fmaf(b.x, b.x, sqj); sqj = fmaf(b.y, b.y, sqj);
                                sqj = fmaf(b.z, b.z, sqj); sqj = fmaf(b.w, b.w, sqj);
                                dot = fmaf(a.x, b.x, dot); dot = fmaf(a.y, b.y, dot);
                                dot = fmaf(a.z, b.z, dot); dot = fmaf(a.w, b.w, dot);
                            }
                            float d2 = fmaxf(sqi + sqj - 2.0f * dot, 0.0f);
                            if (d2 <= 16.0f)
                                local = fmaf(2.0f * corr_fn(d2), maskval(i, j), local);
                        }
                    }
                }
            }
        }
    }

    #pragma unroll
    for (int o = 16; o > 0; o >>= 1) local += __shfl_xor_sync(0xffffffffu, local, o);
    if (lane == 0) wsum[wid] = local;
    __syncthreads();
    if (tid == 0) {
        float s = 0.0f;
        #pragma unroll
        for (int w = 0; w < 8; w++) s += wsum[w];
        g_partials[blockIdx.x] = s;
    }
}

// ---------------- final reduce + closed-form base term ---------------------
__global__ void reduce_kernel(float* __restrict__ out) {
    int t = threadIdx.x;  // 256
    float s = 0.0f;
    for (int i = t; i < NT; i += 256) s += g_partials[i];
    #pragma unroll
    for (int o = 16; o > 0; o >>= 1) s += __shfl_xor_sync(0xffffffffu, s, o);
    __shared__ float ws[8];
    if ((t & 31) == 0) ws[t >> 5] = s;
    __syncthreads();
    if (t == 0) {
        float tot = 0.0f;
        #pragma unroll
        for (int w = 0; w < 8; w++) tot += ws[w];
        // off-diag sim == -1.0027f exactly; sum(mask) = N*(360*POSV + 8855*NEGV)
        double masksum = 9216.0 * (360.0 * (double)POSV + 8855.0 * (double)NEGV);
        double base = (double)(-1.0027f) * masksum;
        out[0] = (float)(((double)tot + base) / 9216.0);
    }
}

extern "C" void kernel_launch(void* const* d_in, const int* in_sizes, int n_in,
                              void* d_out, int out_size) {
    const float* images = (const float*)d_in[0];   // [9216,1,16,16] fp32
    (void)in_sizes; (void)n_in;
    prep_kernel<<<N_PTS * 8 / 256, 256>>>(images);
    pair_kernel<<<NT, 256>>>(images);
    reduce_kernel<<<1, 256>>>((float*)d_out);
}